// round 3
// baseline (speedup 1.0000x reference)
#include <cuda_runtime.h>
#include <math.h>

// Problem constants
#define NB   2      // batch
#define IH   128
#define IW   128
#define IC   192
#define LTOT 4096   // 64*64 patch/query count
#define MQ   4225   // 65*65 extended query/source grid
#define MQP  4352   // padded to 34*128
#define NOUT 768    // 4 parities * 192 channels

// ---------------- scratch (device globals; allocation-free) ----------------
__device__ float g_fd[NB][LTOT][IC];                 // downsampled f, packed [p][c]
__device__ float g_bd[NB][LTOT][IC];                 // downsampled b
__device__ float g_n2[NB][LTOT];                     // per-pixel sum of squares of bd
__device__ float g_norm[NB][LTOT];                   // patch norms
__device__ float g_mm[LTOT];                         // valid-patch mask
__device__ float g_D[NB][(size_t)LTOT * LTOT];       // pixel-dot matrix / fuse temp
__device__ float g_S[NB][(size_t)LTOT * LTOT];       // scores / softmax (in place)
__device__ float g_At[NB][(size_t)MQP * MQP];        // folded attention (A-tilde), padded
__device__ float g_Bp[NB][(size_t)MQP * NOUT];       // parity-gathered b (GEMM B), padded rows
__device__ float g_On[NB][(size_t)MQP * NOUT];       // final GEMM result

// ---------------- K1: downsample + pack + per-pixel |bd|^2 ----------------
__global__ void k_pack(const float* __restrict__ f, const float* __restrict__ b) {
    int i = blockIdx.z;
    int p = blockIdx.x;                 // 0..4095 downsampled pixel
    int x = p >> 6, y = p & 63;
    size_t base = (((size_t)i * IH + 2 * x) * IW + 2 * y) * IC;
    int c = threadIdx.x;                // 0..191
    float fv = f[base + c];
    float bv = b[base + c];
    g_fd[i][p][c] = fv;
    g_bd[i][p][c] = bv;

    __shared__ float sh[192];
    sh[c] = bv * bv;
    __syncthreads();
    if (c < 64) sh[c] += sh[c + 64] + sh[c + 128];
    __syncthreads();
    if (c < 32) {
        float v = sh[c] + sh[c + 32];
        #pragma unroll
        for (int o = 16; o > 0; o >>= 1) v += __shfl_down_sync(0xffffffffu, v, o);
        if (c == 0) g_n2[i][p] = v;
    }
}

// ---------------- K1b: patch norms (3x3 stencil of n2) + mask mm ----------
__global__ void k_norm_mm(const float* __restrict__ mask) {
    int i = blockIdx.z;
    int l = blockIdx.x * 128 + threadIdx.x;   // 0..4095
    int u = l >> 6, v = l & 63;
    float s = 0.f;
    #pragma unroll
    for (int a = -1; a <= 1; ++a)
        #pragma unroll
        for (int bo = -1; bo <= 1; ++bo) {
            int uu = u + a, vv = v + bo;
            if ((unsigned)uu < 64u && (unsigned)vv < 64u)
                s += g_n2[i][uu * 64 + vv];
        }
    g_norm[i][l] = fmaxf(sqrtf(s), 1e-4f);

    if (i == 0) {
        float ms = 0.f;
        #pragma unroll
        for (int a = -1; a <= 1; ++a)
            #pragma unroll
            for (int bo = -1; bo <= 1; ++bo) {
                int uu = u + a, vv = v + bo;
                if ((unsigned)uu < 64u && (unsigned)vv < 64u)
                    ms += mask[(2 * uu) * IW + 2 * vv];
            }
        g_mm[l] = (ms == 0.0f) ? 1.0f : 0.0f;
    }
}

// ---------------- K2: D = fd * bd^T  (NT GEMM, M=N=4096, K=192) -----------
__global__ __launch_bounds__(256, 2)
void k_gemm_D() {
    int i = blockIdx.z;
    const float* A = &g_fd[i][0][0];
    const float* B = &g_bd[i][0][0];
    float* Cm = g_D[i];
    __shared__ float As[8][132];
    __shared__ float Bs[8][132];
    int bm = blockIdx.y << 7, bn = blockIdx.x << 7;
    int t = threadIdx.x, tx = t & 15, ty = t >> 4;
    int lrow = t >> 1, lkq = (t & 1) << 2;
    float acc[8][8] = {};

    for (int k0 = 0; k0 < 192; k0 += 8) {
        float4 av = *(const float4*)(A + (size_t)(bm + lrow) * 192 + k0 + lkq);
        float4 bv = *(const float4*)(B + (size_t)(bn + lrow) * 192 + k0 + lkq);
        As[lkq + 0][lrow] = av.x; As[lkq + 1][lrow] = av.y;
        As[lkq + 2][lrow] = av.z; As[lkq + 3][lrow] = av.w;
        Bs[lkq + 0][lrow] = bv.x; Bs[lkq + 1][lrow] = bv.y;
        Bs[lkq + 2][lrow] = bv.z; Bs[lkq + 3][lrow] = bv.w;
        __syncthreads();
        #pragma unroll
        for (int kk = 0; kk < 8; ++kk) {
            float ar[8], br[8];
            *(float4*)&ar[0] = *(const float4*)&As[kk][ty * 8];
            *(float4*)&ar[4] = *(const float4*)&As[kk][ty * 8 + 4];
            *(float4*)&br[0] = *(const float4*)&Bs[kk][tx * 8];
            *(float4*)&br[4] = *(const float4*)&Bs[kk][tx * 8 + 4];
            #pragma unroll
            for (int m = 0; m < 8; ++m)
                #pragma unroll
                for (int n = 0; n < 8; ++n)
                    acc[m][n] = fmaf(ar[m], br[n], acc[m][n]);
        }
        __syncthreads();
    }
    #pragma unroll
    for (int m = 0; m < 8; ++m) {
        float* dst = Cm + (size_t)(bm + ty * 8 + m) * 4096 + bn + tx * 8;
        *(float4*)dst       = make_float4(acc[m][0], acc[m][1], acc[m][2], acc[m][3]);
        *(float4*)(dst + 4) = make_float4(acc[m][4], acc[m][5], acc[m][6], acc[m][7]);
    }
}

// ---------------- K3: S[q,l] = 9-tap diagonal stencil of D / norm[l] ------
__global__ void k_score() {
    int i = blockIdx.z;
    int idx = blockIdx.x * 256 + threadIdx.x;    // < 16777216
    int q = idx >> 12, l = idx & 4095;
    int x = q >> 6, y = q & 63, u = l >> 6, v = l & 63;
    const float* D = g_D[i];
    float s = 0.f;
    #pragma unroll
    for (int a = -1; a <= 1; ++a) {
        if ((unsigned)(x + a) < 64u && (unsigned)(u + a) < 64u) {
            #pragma unroll
            for (int bo = -1; bo <= 1; ++bo) {
                if ((unsigned)(y + bo) < 64u && (unsigned)(v + bo) < 64u) {
                    int off = a * 64 + bo;
                    s += D[(size_t)(q + off) * 4096 + (l + off)];
                }
            }
        }
    }
    g_S[i][(size_t)q * 4096 + l] = s / g_norm[i][l];
}

// ---------------- K4: fuse pass 1 (flat-index diagonal, S -> D) -----------
__global__ void k_fuse1() {
    int i = blockIdx.z;
    int idx = blockIdx.x * 256 + threadIdx.x;
    int p = idx >> 12, q = idx & 4095;
    const float* S = g_S[i];
    float s = 0.f;
    #pragma unroll
    for (int d = -1; d <= 1; ++d) {
        int pp = p + d, qq = q + d;
        if ((unsigned)pp < 4096u && (unsigned)qq < 4096u)
            s += S[(size_t)pp * 4096 + qq];
    }
    g_D[i][(size_t)p * 4096 + q] = s;
}

// ------- K5: fuse pass 2 (transposed flattening, D(F1) -> S(final)) -------
__global__ void k_fuse2() {
    int i = blockIdx.z;
    int idx = blockIdx.x * 256 + threadIdx.x;
    int q = idx >> 12, l = idx & 4095;        // q=(i_,j_) row-major h,w; l=(ib,jb)
    int i_ = q >> 6, j_ = q & 63;
    int ib = l >> 6, jb = l & 63;
    int pt = j_ * 64 + i_;                    // transposed flat index
    int qt = jb * 64 + ib;
    const float* F1 = g_D[i];
    float s = 0.f;
    #pragma unroll
    for (int d = -1; d <= 1; ++d) {
        int p2 = pt + d, q2 = qt + d;
        if ((unsigned)p2 < 4096u && (unsigned)q2 < 4096u) {
            int i2 = p2 & 63, j2 = p2 >> 6;   // p2 = j'*64 + i'
            int ib2 = q2 & 63, jb2 = q2 >> 6;
            s += F1[(size_t)(i2 * 64 + j2) * 4096 + (ib2 * 64 + jb2)];
        }
    }
    g_S[i][(size_t)q * 4096 + l] = s;
}

// ---------------- K6: masked softmax over l (in place on g_S) -------------
__global__ void k_softmax() {
    int i = blockIdx.z, q = blockIdx.x;
    float* row = g_S[i] + (size_t)q * 4096;
    int t = threadIdx.x;   // 256
    float vals[16];
    float mx = -3.4e38f;
    #pragma unroll
    for (int j = 0; j < 16; ++j) {
        int l = t + j * 256;
        float v = row[l] * g_mm[l] * 10.0f;
        vals[j] = v;
        mx = fmaxf(mx, v);
    }
    __shared__ float sh[256];
    sh[t] = mx; __syncthreads();
    #pragma unroll
    for (int s = 128; s > 0; s >>= 1) { if (t < s) sh[t] = fmaxf(sh[t], sh[t + s]); __syncthreads(); }
    mx = sh[0];
    __syncthreads();
    float sum = 0.f;
    #pragma unroll
    for (int j = 0; j < 16; ++j) { vals[j] = expf(vals[j] - mx); sum += vals[j]; }
    sh[t] = sum; __syncthreads();
    #pragma unroll
    for (int s = 128; s > 0; s >>= 1) { if (t < s) sh[t] += sh[t + s]; __syncthreads(); }
    float inv = 1.0f / sh[0];
    #pragma unroll
    for (int j = 0; j < 16; ++j) {
        int l = t + j * 256;
        row[l] = vals[j] * inv * g_mm[l];
    }
}

// ------ K7: build A-tilde: 4-term shifted sum of softmaxed A --------------
// At[(x0,y0),(u',v')] = sum_{a,b in {0,1}} A[(x0-a,y0-b),(u'-a,v'-b)] (OOB->0)
__global__ void k_Abuild() {
    int i = blockIdx.z;
    int q0 = blockIdx.y;                       // 0..4224
    int lp = blockIdx.x * 256 + threadIdx.x;   // 0..4351
    if (lp >= MQ) return;
    int x0 = q0 / 65, y0 = q0 % 65;
    int up = lp / 65, vp = lp % 65;
    const float* A = g_S[i];
    float s = 0.f;
    #pragma unroll
    for (int a = 0; a < 2; ++a) {
        int xr = x0 - a, ur = up - a;
        if ((unsigned)xr < 64u && (unsigned)ur < 64u) {
            #pragma unroll
            for (int bo = 0; bo < 2; ++bo) {
                int yr = y0 - bo, vr = vp - bo;
                if ((unsigned)yr < 64u && (unsigned)vr < 64u)
                    s += A[(size_t)(xr * 64 + yr) * 4096 + (ur * 64 + vr)];
            }
        }
    }
    g_At[i][(size_t)q0 * MQP + lp] = s;
}

// ------ K8: build parity-gathered B: Bp[l'][(par,c)] = b[2u'+rx-1,2v'+ry-1,c]
__global__ void k_Bbuild(const float* __restrict__ b) {
    int i = blockIdx.z;
    int idx = blockIdx.x * 256 + threadIdx.x;   // < 4225*768
    if (idx >= MQ * NOUT) return;
    int lp = idx / NOUT, n = idx - lp * NOUT;
    int par = n / IC, c = n - par * IC;
    int rx = par >> 1, ry = par & 1;
    int up = lp / 65, vp = lp % 65;
    int X = 2 * up + rx - 1, Y = 2 * vp + ry - 1;
    float val = 0.f;
    if ((unsigned)X < 128u && (unsigned)Y < 128u)
        val = b[(((size_t)i * IH + X) * IW + Y) * IC + c];
    g_Bp[i][(size_t)lp * NOUT + n] = val;
}

// ------ K9: On = At(4352x4352) * Bp(4352x768)   (NN GEMM) -----------------
__global__ __launch_bounds__(256, 2)
void k_gemm_out() {
    int i = blockIdx.z;
    const float* A = g_At[i];
    const float* B = g_Bp[i];
    float* Cm = g_On[i];
    __shared__ float As[8][132];
    __shared__ float Bs[8][132];
    int bm = blockIdx.y << 7, bn = blockIdx.x << 7;
    int t = threadIdx.x, tx = t & 15, ty = t >> 4;
    int arow = t >> 1, akq = (t & 1) << 2;
    int bkr = t >> 5, bnc = (t & 31) << 2;
    float acc[8][8] = {};

    for (int k0 = 0; k0 < MQP; k0 += 8) {
        float4 av = *(const float4*)(A + (size_t)(bm + arow) * MQP + k0 + akq);
        float4 bv = *(const float4*)(B + (size_t)(k0 + bkr) * NOUT + bn + bnc);
        As[akq + 0][arow] = av.x; As[akq + 1][arow] = av.y;
        As[akq + 2][arow] = av.z; As[akq + 3][arow] = av.w;
        *(float4*)&Bs[bkr][bnc] = bv;
        __syncthreads();
        #pragma unroll
        for (int kk = 0; kk < 8; ++kk) {
            float ar[8], br[8];
            *(float4*)&ar[0] = *(const float4*)&As[kk][ty * 8];
            *(float4*)&ar[4] = *(const float4*)&As[kk][ty * 8 + 4];
            *(float4*)&br[0] = *(const float4*)&Bs[kk][tx * 8];
            *(float4*)&br[4] = *(const float4*)&Bs[kk][tx * 8 + 4];
            #pragma unroll
            for (int m = 0; m < 8; ++m)
                #pragma unroll
                for (int n = 0; n < 8; ++n)
                    acc[m][n] = fmaf(ar[m], br[n], acc[m][n]);
        }
        __syncthreads();
    }
    #pragma unroll
    for (int m = 0; m < 8; ++m) {
        float* dst = Cm + (size_t)(bm + ty * 8 + m) * NOUT + bn + tx * 8;
        *(float4*)dst       = make_float4(acc[m][0], acc[m][1], acc[m][2], acc[m][3]);
        *(float4*)(dst + 4) = make_float4(acc[m][4], acc[m][5], acc[m][6], acc[m][7]);
    }
}

// ---------------- K10: final parity gather -> output ----------------------
__global__ void k_output(float* __restrict__ out) {
    int i = blockIdx.z;
    int idx = blockIdx.x * 256 + threadIdx.x;   // < 128*128*192
    int c = idx % IC;
    int rest = idx / IC;
    int Y = rest % IW, X = rest / IW;
    int rx = (X + 1) & 1, ry = (Y + 1) & 1;
    int x0 = (X + 1 - rx) >> 1, y0 = (Y + 1 - ry) >> 1;
    float v = g_On[i][(size_t)(x0 * 65 + y0) * NOUT + ((rx << 1) | ry) * IC + c];
    out[(size_t)i * (IH * IW * IC) + idx] = 0.25f * v;
}

// ---------------- launch --------------------------------------------------
extern "C" void kernel_launch(void* const* d_in, const int* in_sizes, int n_in,
                              void* d_out, int out_size) {
    const float* f    = (const float*)d_in[0];
    const float* b    = (const float*)d_in[1];
    const float* mask = (const float*)d_in[2];
    float* out = (float*)d_out;

    k_pack    <<<dim3(4096, 1, NB), 192>>>(f, b);
    k_norm_mm <<<dim3(32,   1, NB), 128>>>(mask);
    k_gemm_D  <<<dim3(32,  32, NB), 256>>>();
    k_score   <<<dim3(65536,1, NB), 256>>>();
    k_fuse1   <<<dim3(65536,1, NB), 256>>>();
    k_fuse2   <<<dim3(65536,1, NB), 256>>>();
    k_softmax <<<dim3(4096, 1, NB), 256>>>();
    k_Abuild  <<<dim3(17, MQ, NB), 256>>>();
    k_Bbuild  <<<dim3((MQ * NOUT + 255) / 256, 1, NB), 256>>>(b);
    k_gemm_out<<<dim3(6,  34, NB), 256>>>();
    k_output  <<<dim3(12288, 1, NB), 256>>>(out);
}

// round 5
// speedup vs baseline: 1.6487x; 1.6487x over previous
#include <cuda_runtime.h>
#include <cuda_bf16.h>
#include <math.h>
#include <stdint.h>

#define NB   2
#define IH   128
#define IW   128
#define IC   192
#define LTOT 4096
#define MQ   4225   // 65*65
#define MQP  4352   // 34*128
#define NOUT 768
#define KD   192

// ---------------- scratch ----------------
__device__ __nv_bfloat16 g_fdh[NB][LTOT][KD], g_fdl[NB][LTOT][KD];
__device__ __nv_bfloat16 g_bdh[NB][LTOT][KD], g_bdl[NB][LTOT][KD];
__device__ float g_n2[NB][LTOT];
__device__ float g_norm[NB][LTOT];
__device__ float g_mm[LTOT];
__device__ float g_D[NB][(size_t)LTOT * LTOT];
__device__ float g_S[NB][(size_t)LTOT * LTOT];
__device__ __nv_bfloat16 g_Ath[NB][(size_t)MQP * MQP];
__device__ __nv_bfloat16 g_Atl[NB][(size_t)MQP * MQP];
__device__ __nv_bfloat16 g_Bth[NB][(size_t)NOUT * MQP];
__device__ __nv_bfloat16 g_Btl[NB][(size_t)NOUT * MQP];
__device__ float g_On[NB][(size_t)MQP * NOUT];

__device__ __forceinline__ void split_bf16(float v, __nv_bfloat16& h, __nv_bfloat16& l) {
    h = __float2bfloat16(v);
    l = __float2bfloat16(v - __bfloat162float(h));
}

#define MMA(ac, a, bb) \
    asm volatile("mma.sync.aligned.m16n8k16.row.col.f32.bf16.bf16.f32 " \
        "{%0,%1,%2,%3}, {%4,%5,%6,%7}, {%8,%9}, {%0,%1,%2,%3};" \
        : "+f"((ac)[0]), "+f"((ac)[1]), "+f"((ac)[2]), "+f"((ac)[3]) \
        : "r"((a)[0]), "r"((a)[1]), "r"((a)[2]), "r"((a)[3]), \
          "r"((bb)[0]), "r"((bb)[1]))

// ---------------- K1: downsample + pack bf16 hi/lo + |bd|^2 ---------------
__global__ void k_pack(const float* __restrict__ f, const float* __restrict__ b) {
    int i = blockIdx.z, p = blockIdx.x;
    int x = p >> 6, y = p & 63;
    size_t base = (((size_t)i * IH + 2 * x) * IW + 2 * y) * IC;
    int c = threadIdx.x;
    float fv = f[base + c], bv = b[base + c];
    __nv_bfloat16 h, l;
    split_bf16(fv, h, l); g_fdh[i][p][c] = h; g_fdl[i][p][c] = l;
    split_bf16(bv, h, l); g_bdh[i][p][c] = h; g_bdl[i][p][c] = l;

    __shared__ float sh[192];
    sh[c] = bv * bv;
    __syncthreads();
    if (c < 64) sh[c] += sh[c + 64] + sh[c + 128];
    __syncthreads();
    if (c < 32) {
        float v = sh[c] + sh[c + 32];
        #pragma unroll
        for (int o = 16; o > 0; o >>= 1) v += __shfl_down_sync(0xffffffffu, v, o);
        if (c == 0) g_n2[i][p] = v;
    }
}

// ---------------- K1b: patch norms + mask ----------------------------------
__global__ void k_norm_mm(const float* __restrict__ mask) {
    int i = blockIdx.z;
    int l = blockIdx.x * 128 + threadIdx.x;
    int u = l >> 6, v = l & 63;
    float s = 0.f;
    #pragma unroll
    for (int a = -1; a <= 1; ++a)
        #pragma unroll
        for (int bo = -1; bo <= 1; ++bo) {
            int uu = u + a, vv = v + bo;
            if ((unsigned)uu < 64u && (unsigned)vv < 64u) s += g_n2[i][uu * 64 + vv];
        }
    g_norm[i][l] = fmaxf(sqrtf(s), 1e-4f);
    if (i == 0) {
        float ms = 0.f;
        #pragma unroll
        for (int a = -1; a <= 1; ++a)
            #pragma unroll
            for (int bo = -1; bo <= 1; ++bo) {
                int uu = u + a, vv = v + bo;
                if ((unsigned)uu < 64u && (unsigned)vv < 64u) ms += mask[(2 * uu) * IW + 2 * vv];
            }
        g_mm[l] = (ms == 0.0f) ? 1.0f : 0.0f;
    }
}

// ---- split-bf16 HMMA GEMM: C[128x128/CTA] = A*B^T (A:[M][K], B:[N][K]) ----
// smem tiles: 128 rows x 32 halves, padded row stride 40 halves (bank-safe).
#define TSTR 40
#define TILEB (128 * TSTR)   // halves per tile

__device__ __forceinline__ void ld_tile(const __nv_bfloat16* __restrict__ src,
                                        int ld, int row0, int k0,
                                        __nv_bfloat16* dst, int tid) {
    #pragma unroll
    for (int j = 0; j < 2; ++j) {
        int idx = j * 256 + tid;            // 0..511
        int r = idx >> 2, cc = idx & 3;
        const uint4 v = *(const uint4*)(src + (size_t)(row0 + r) * ld + k0 + cc * 8);
        *(uint4*)(dst + r * TSTR + cc * 8) = v;
    }
}

template<int MODE>
__global__ __launch_bounds__(256) void k_gemm_mma() {
    constexpr int KIT = (MODE == 0) ? 6 : 136;      // K/32
    constexpr int LDA = (MODE == 0) ? KD : MQP;
    constexpr int LDC = (MODE == 0) ? 4096 : NOUT;
    __shared__ __nv_bfloat16 sm[4 * TILEB];
    __nv_bfloat16* sAh = sm;
    __nv_bfloat16* sAl = sm + TILEB;
    __nv_bfloat16* sBh = sm + 2 * TILEB;
    __nv_bfloat16* sBl = sm + 3 * TILEB;

    int i = blockIdx.z, tid = threadIdx.x;
    int wid = tid >> 5, lane = tid & 31;
    int wm = wid & 1, wn = wid >> 1;        // warps 2 x 4
    int g = lane >> 2, t = lane & 3;
    int bm = blockIdx.y << 7, bn = blockIdx.x << 7;

    const __nv_bfloat16 *Ah, *Al, *Bh, *Bl;
    float* Cm;
    if (MODE == 0) {
        Ah = &g_fdh[i][0][0]; Al = &g_fdl[i][0][0];
        Bh = &g_bdh[i][0][0]; Bl = &g_bdl[i][0][0]; Cm = g_D[i];
    } else {
        Ah = g_Ath[i]; Al = g_Atl[i];
        Bh = g_Bth[i]; Bl = g_Btl[i]; Cm = g_On[i];
    }

    float acc[4][4][4] = {};
    const uint32_t* sAh32 = (const uint32_t*)sAh;
    const uint32_t* sAl32 = (const uint32_t*)sAl;
    const uint32_t* sBh32 = (const uint32_t*)sBh;
    const uint32_t* sBl32 = (const uint32_t*)sBl;
    const int HTSTR = TSTR / 2;             // words per row

    for (int it = 0; it < KIT; ++it) {
        int k0 = it << 5;
        __syncthreads();
        ld_tile(Ah, LDA, bm, k0, sAh, tid);
        ld_tile(Al, LDA, bm, k0, sAl, tid);
        ld_tile(Bh, LDA, bn, k0, sBh, tid);
        ld_tile(Bl, LDA, bn, k0, sBl, tid);
        __syncthreads();
        #pragma unroll
        for (int ks = 0; ks < 2; ++ks) {
            uint32_t ah[4][4], al[4][4], bh[4][2], bl[4][2];
            #pragma unroll
            for (int mi = 0; mi < 4; ++mi) {
                int base = (wm * 64 + mi * 16 + g) * HTSTR + ks * 8 + t;
                ah[mi][0] = sAh32[base];
                ah[mi][1] = sAh32[base + 8 * HTSTR];
                ah[mi][2] = sAh32[base + 4];
                ah[mi][3] = sAh32[base + 8 * HTSTR + 4];
                al[mi][0] = sAl32[base];
                al[mi][1] = sAl32[base + 8 * HTSTR];
                al[mi][2] = sAl32[base + 4];
                al[mi][3] = sAl32[base + 8 * HTSTR + 4];
            }
            #pragma unroll
            for (int ni = 0; ni < 4; ++ni) {
                int base = (wn * 32 + ni * 8 + g) * HTSTR + ks * 8 + t;
                bh[ni][0] = sBh32[base]; bh[ni][1] = sBh32[base + 4];
                bl[ni][0] = sBl32[base]; bl[ni][1] = sBl32[base + 4];
            }
            #pragma unroll
            for (int mi = 0; mi < 4; ++mi)
                #pragma unroll
                for (int ni = 0; ni < 4; ++ni) {
                    MMA(acc[mi][ni], ah[mi], bh[ni]);
                    MMA(acc[mi][ni], ah[mi], bl[ni]);
                    MMA(acc[mi][ni], al[mi], bh[ni]);
                }
        }
    }
    #pragma unroll
    for (int mi = 0; mi < 4; ++mi)
        #pragma unroll
        for (int ni = 0; ni < 4; ++ni) {
            int row = bm + wm * 64 + mi * 16 + g;
            int col = bn + wn * 32 + ni * 8 + 2 * t;
            *(float2*)(Cm + (size_t)row * LDC + col)       = make_float2(acc[mi][ni][0], acc[mi][ni][1]);
            *(float2*)(Cm + (size_t)(row + 8) * LDC + col) = make_float2(acc[mi][ni][2], acc[mi][ni][3]);
        }
}

// ---------------- K3: S[q,l] = 9-tap diagonal stencil of D / norm[l] ------
__global__ void k_score() {
    int i = blockIdx.z;
    int idx = blockIdx.x * 256 + threadIdx.x;
    int q = idx >> 12, l = idx & 4095;
    int x = q >> 6, y = q & 63, u = l >> 6, v = l & 63;
    const float* D = g_D[i];
    float s = 0.f;
    #pragma unroll
    for (int a = -1; a <= 1; ++a) {
        if ((unsigned)(x + a) < 64u && (unsigned)(u + a) < 64u) {
            #pragma unroll
            for (int bo = -1; bo <= 1; ++bo) {
                if ((unsigned)(y + bo) < 64u && (unsigned)(v + bo) < 64u) {
                    int off = a * 64 + bo;
                    s += D[(size_t)(q + off) * 4096 + (l + off)];
                }
            }
        }
    }
    g_S[i][(size_t)q * 4096 + l] = s / g_norm[i][l];
}

// ---------------- K4: fuse pass 1 ------------------------------------------
__global__ void k_fuse1() {
    int i = blockIdx.z;
    int idx = blockIdx.x * 256 + threadIdx.x;
    int p = idx >> 12, q = idx & 4095;
    const float* S = g_S[i];
    float s = 0.f;
    #pragma unroll
    for (int d = -1; d <= 1; ++d) {
        int pp = p + d, qq = q + d;
        if ((unsigned)pp < 4096u && (unsigned)qq < 4096u) s += S[(size_t)pp * 4096 + qq];
    }
    g_D[i][(size_t)p * 4096 + q] = s;
}

// ---------------- K5: fuse pass 2 (transposed flattening) ------------------
__global__ void k_fuse2() {
    int i = blockIdx.z;
    int idx = blockIdx.x * 256 + threadIdx.x;
    int q = idx >> 12, l = idx & 4095;
    int i_ = q >> 6, j_ = q & 63;
    int ib = l >> 6, jb = l & 63;
    int pt = j_ * 64 + i_, qt = jb * 64 + ib;
    const float* F1 = g_D[i];
    float s = 0.f;
    #pragma unroll
    for (int d = -1; d <= 1; ++d) {
        int p2 = pt + d, q2 = qt + d;
        if ((unsigned)p2 < 4096u && (unsigned)q2 < 4096u) {
            int i2 = p2 & 63, j2 = p2 >> 6;
            int ib2 = q2 & 63, jb2 = q2 >> 6;
            s += F1[(size_t)(i2 * 64 + j2) * 4096 + (ib2 * 64 + jb2)];
        }
    }
    g_S[i][(size_t)q * 4096 + l] = s;
}

// ---------------- K6: masked softmax ----------------------------------------
__global__ void k_softmax() {
    int i = blockIdx.z, q = blockIdx.x;
    float* row = g_S[i] + (size_t)q * 4096;
    int t = threadIdx.x;
    float vals[16];
    float mx = -3.4e38f;
    #pragma unroll
    for (int j = 0; j < 16; ++j) {
        int l = t + j * 256;
        float v = row[l] * g_mm[l] * 10.0f;
        vals[j] = v; mx = fmaxf(mx, v);
    }
    __shared__ float sh[256];
    sh[t] = mx; __syncthreads();
    #pragma unroll
    for (int s = 128; s > 0; s >>= 1) { if (t < s) sh[t] = fmaxf(sh[t], sh[t + s]); __syncthreads(); }
    mx = sh[0]; __syncthreads();
    float sum = 0.f;
    #pragma unroll
    for (int j = 0; j < 16; ++j) { vals[j] = expf(vals[j] - mx); sum += vals[j]; }
    sh[t] = sum; __syncthreads();
    #pragma unroll
    for (int s = 128; s > 0; s >>= 1) { if (t < s) sh[t] += sh[t + s]; __syncthreads(); }
    float inv = 1.0f / sh[0];
    #pragma unroll
    for (int j = 0; j < 16; ++j) {
        int l = t + j * 256;
        row[l] = vals[j] * inv * g_mm[l];
    }
}

// ------ K7: build A-tilde (bf16 hi/lo) --------------------------------------
__global__ void k_Abuild() {
    int i = blockIdx.z;
    int q0 = blockIdx.y;
    int lp = blockIdx.x * 256 + threadIdx.x;   // 0..4351
    int x0 = q0 / 65, y0 = q0 % 65;
    int up = lp / 65, vp = lp % 65;
    const float* A = g_S[i];
    float s = 0.f;
    #pragma unroll
    for (int a = 0; a < 2; ++a) {
        int xr = x0 - a, ur = up - a;
        if ((unsigned)xr < 64u && (unsigned)ur < 64u) {
            #pragma unroll
            for (int bo = 0; bo < 2; ++bo) {
                int yr = y0 - bo, vr = vp - bo;
                if ((unsigned)yr < 64u && (unsigned)vr < 64u)
                    s += A[(size_t)(xr * 64 + yr) * 4096 + (ur * 64 + vr)];
            }
        }
    }
    __nv_bfloat16 h, l;
    split_bf16(s, h, l);
    g_Ath[i][(size_t)q0 * MQP + lp] = h;
    g_Atl[i][(size_t)q0 * MQP + lp] = l;
}

// ------ K8: build Bt[n][k'] (bf16 hi/lo, K-major) ---------------------------
__global__ void k_Btbuild(const float* __restrict__ b) {
    int i = blockIdx.z;
    int n = blockIdx.y;                          // 0..767
    int lp = blockIdx.x * 256 + threadIdx.x;     // 0..4351
    int par = n / IC, c = n - par * IC;
    int rx = par >> 1, ry = par & 1;
    int up = lp / 65, vp = lp % 65;
    int X = 2 * up + rx - 1, Y = 2 * vp + ry - 1;
    float val = 0.f;
    if (lp < MQ && (unsigned)X < 128u && (unsigned)Y < 128u)
        val = b[(((size_t)i * IH + X) * IW + Y) * IC + c];
    __nv_bfloat16 h, l;
    split_bf16(val, h, l);
    g_Bth[i][(size_t)n * MQP + lp] = h;
    g_Btl[i][(size_t)n * MQP + lp] = l;
}

// ---------------- K10: final parity gather -> output ------------------------
__global__ void k_output(float* __restrict__ out) {
    int i = blockIdx.z;
    int idx = blockIdx.x * 256 + threadIdx.x;
    int c = idx % IC;
    int rest = idx / IC;
    int Y = rest % IW, X = rest / IW;
    int rx = (X + 1) & 1, ry = (Y + 1) & 1;
    int x0 = (X + 1 - rx) >> 1, y0 = (Y + 1 - ry) >> 1;
    float v = g_On[i][(size_t)(x0 * 65 + y0) * NOUT + ((rx << 1) | ry) * IC + c];
    out[(size_t)i * (IH * IW * IC) + idx] = 0.25f * v;
}

// ---------------- launch -----------------------------------------------------
extern "C" void kernel_launch(void* const* d_in, const int* in_sizes, int n_in,
                              void* d_out, int out_size) {
    const float* f    = (const float*)d_in[0];
    const float* b    = (const float*)d_in[1];
    const float* mask = (const float*)d_in[2];
    float* out = (float*)d_out;

    k_pack    <<<dim3(4096, 1, NB), 192>>>(f, b);
    k_norm_mm <<<dim3(32,   1, NB), 128>>>(mask);
    k_gemm_mma<0><<<dim3(32, 32, NB), 256>>>();
    k_score   <<<dim3(65536, 1, NB), 256>>>();
    k_fuse1   <<<dim3(65536, 1, NB), 256>>>();
    k_fuse2   <<<dim3(65536, 1, NB), 256>>>();
    k_softmax <<<dim3(4096, 1, NB), 256>>>();
    k_Abuild  <<<dim3(17, MQ, NB), 256>>>();
    k_Btbuild <<<dim3(17, NOUT, NB), 256>>>(b);
    k_gemm_mma<1><<<dim3(6, 34, NB), 256>>>();
    k_output  <<<dim3(12288, 1, NB), 256>>>(out);
}

// round 6
// speedup vs baseline: 2.0116x; 1.2201x over previous
#include <cuda_runtime.h>
#include <cuda_bf16.h>
#include <math.h>
#include <stdint.h>

#define NB   2
#define IH   128
#define IW   128
#define IC   192
#define LTOT 4096
#define MQ   4225   // 65*65
#define MQP  4352   // 34*128
#define NOUT 768
#define KD   192

// ---------------- scratch ----------------
__device__ __nv_bfloat16 g_fdh[NB][LTOT][KD], g_fdl[NB][LTOT][KD];
__device__ __nv_bfloat16 g_bdh[NB][LTOT][KD], g_bdl[NB][LTOT][KD];
__device__ float g_n2[NB][LTOT];
__device__ float g_norm[NB][LTOT];
__device__ float g_mmT[LTOT];                       // mask, transposed index
__device__ float g_D[NB][(size_t)LTOT * LTOT];      // D, then F1
__device__ float g_S[NB][(size_t)LTOT * LTOT];      // S, then AT (attention, transposed)
__device__ __nv_bfloat16 g_Ath[NB][(size_t)MQP * MQP];
__device__ __nv_bfloat16 g_Atl[NB][(size_t)MQP * MQP];
__device__ __nv_bfloat16 g_Bth[NB][(size_t)NOUT * MQP];
__device__ __nv_bfloat16 g_Btl[NB][(size_t)NOUT * MQP];
__device__ float g_On[NB][(size_t)MQP * NOUT];

__device__ __forceinline__ void split_bf16(float v, __nv_bfloat16& h, __nv_bfloat16& l) {
    h = __float2bfloat16(v);
    l = __float2bfloat16(v - __bfloat162float(h));
}
__device__ __forceinline__ uint32_t smem_u32(const void* p) {
    uint32_t a;
    asm("{ .reg .u64 t; cvta.to.shared.u64 t, %1; cvt.u32.u64 %0, t; }" : "=r"(a) : "l"(p));
    return a;
}

#define MMA(ac, a, bb) \
    asm volatile("mma.sync.aligned.m16n8k16.row.col.f32.bf16.bf16.f32 " \
        "{%0,%1,%2,%3}, {%4,%5,%6,%7}, {%8,%9}, {%0,%1,%2,%3};" \
        : "+f"((ac)[0]), "+f"((ac)[1]), "+f"((ac)[2]), "+f"((ac)[3]) \
        : "r"((a)[0]), "r"((a)[1]), "r"((a)[2]), "r"((a)[3]), \
          "r"((bb)[0]), "r"((bb)[1]))

// ---------------- K1: downsample + pack bf16 hi/lo + |bd|^2 ---------------
__global__ void k_pack(const float* __restrict__ f, const float* __restrict__ b) {
    int i = blockIdx.z, p = blockIdx.x;
    int x = p >> 6, y = p & 63;
    size_t base = (((size_t)i * IH + 2 * x) * IW + 2 * y) * IC;
    int c = threadIdx.x;
    float fv = f[base + c], bv = b[base + c];
    __nv_bfloat16 h, l;
    split_bf16(fv, h, l); g_fdh[i][p][c] = h; g_fdl[i][p][c] = l;
    split_bf16(bv, h, l); g_bdh[i][p][c] = h; g_bdl[i][p][c] = l;

    __shared__ float sh[192];
    sh[c] = bv * bv;
    __syncthreads();
    if (c < 64) sh[c] += sh[c + 64] + sh[c + 128];
    __syncthreads();
    if (c < 32) {
        float v = sh[c] + sh[c + 32];
        #pragma unroll
        for (int o = 16; o > 0; o >>= 1) v += __shfl_down_sync(0xffffffffu, v, o);
        if (c == 0) g_n2[i][p] = v;
    }
}

// ---------------- K1b: patch norms + transposed mask ------------------------
__global__ void k_norm_mm(const float* __restrict__ mask) {
    int i = blockIdx.z;
    int l = blockIdx.x * 128 + threadIdx.x;
    int u = l >> 6, v = l & 63;
    float s = 0.f;
    #pragma unroll
    for (int a = -1; a <= 1; ++a)
        #pragma unroll
        for (int bo = -1; bo <= 1; ++bo) {
            int uu = u + a, vv = v + bo;
            if ((unsigned)uu < 64u && (unsigned)vv < 64u) s += g_n2[i][uu * 64 + vv];
        }
    g_norm[i][l] = fmaxf(sqrtf(s), 1e-4f);
    if (i == 0) {
        float ms = 0.f;
        #pragma unroll
        for (int a = -1; a <= 1; ++a)
            #pragma unroll
            for (int bo = -1; bo <= 1; ++bo) {
                int uu = u + a, vv = v + bo;
                if ((unsigned)uu < 64u && (unsigned)vv < 64u) ms += mask[(2 * uu) * IW + 2 * vv];
            }
        g_mmT[((l & 63) << 6) | (l >> 6)] = (ms == 0.0f) ? 1.0f : 0.0f;
    }
}

// ---- split-bf16 HMMA GEMM, cp.async double-buffered -----------------------
#define TSTR 40
#define TILEB (128 * TSTR)

__device__ __forceinline__ void cp_tile(const __nv_bfloat16* __restrict__ src,
                                        int ld, int row0, int k0,
                                        __nv_bfloat16* dst, int tid) {
    #pragma unroll
    for (int j = 0; j < 2; ++j) {
        int idx = j * 256 + tid;
        int r = idx >> 2, cc = idx & 3;
        uint32_t d = smem_u32(dst + r * TSTR + cc * 8);
        const void* s = src + (size_t)(row0 + r) * ld + k0 + cc * 8;
        asm volatile("cp.async.ca.shared.global [%0], [%1], 16;" :: "r"(d), "l"(s));
    }
}

template<int MODE>
__global__ __launch_bounds__(256) void k_gemm_mma() {
    constexpr int KIT = (MODE == 0) ? 6 : 136;
    constexpr int LDA = (MODE == 0) ? KD : MQP;
    constexpr int LDC = (MODE == 0) ? 4096 : NOUT;
    extern __shared__ __nv_bfloat16 smg[];   // 2 stages * 4 tiles * TILEB

    int i = blockIdx.z, tid = threadIdx.x;
    int wid = tid >> 5, lane = tid & 31;
    int wm = wid & 1, wn = wid >> 1;
    int g = lane >> 2, t = lane & 3;
    int bm = blockIdx.y << 7, bn = blockIdx.x << 7;

    const __nv_bfloat16 *Ah, *Al, *Bh, *Bl;
    float* Cm;
    if (MODE == 0) {
        Ah = &g_fdh[i][0][0]; Al = &g_fdl[i][0][0];
        Bh = &g_bdh[i][0][0]; Bl = &g_bdl[i][0][0]; Cm = g_D[i];
    } else {
        Ah = g_Ath[i]; Al = g_Atl[i];
        Bh = g_Bth[i]; Bl = g_Btl[i]; Cm = g_On[i];
    }

    float acc[4][4][4] = {};
    const int HTSTR = TSTR / 2;

    // prologue
    {
        __nv_bfloat16* b0 = smg;
        cp_tile(Ah, LDA, bm, 0, b0, tid);
        cp_tile(Al, LDA, bm, 0, b0 + TILEB, tid);
        cp_tile(Bh, LDA, bn, 0, b0 + 2 * TILEB, tid);
        cp_tile(Bl, LDA, bn, 0, b0 + 3 * TILEB, tid);
        asm volatile("cp.async.commit_group;" ::: "memory");
    }

    for (int it = 0; it < KIT; ++it) {
        int st = it & 1;
        if (it + 1 < KIT) {
            __nv_bfloat16* b0 = smg + (st ^ 1) * 4 * TILEB;
            int k0 = (it + 1) << 5;
            cp_tile(Ah, LDA, bm, k0, b0, tid);
            cp_tile(Al, LDA, bm, k0, b0 + TILEB, tid);
            cp_tile(Bh, LDA, bn, k0, b0 + 2 * TILEB, tid);
            cp_tile(Bl, LDA, bn, k0, b0 + 3 * TILEB, tid);
            asm volatile("cp.async.commit_group;" ::: "memory");
            asm volatile("cp.async.wait_group 1;" ::: "memory");
        } else {
            asm volatile("cp.async.wait_group 0;" ::: "memory");
        }
        __syncthreads();
        const uint32_t* sAh32 = (const uint32_t*)(smg + st * 4 * TILEB);
        const uint32_t* sAl32 = sAh32 + TILEB / 2;
        const uint32_t* sBh32 = sAh32 + TILEB;
        const uint32_t* sBl32 = sAh32 + 3 * TILEB / 2;
        #pragma unroll
        for (int ks = 0; ks < 2; ++ks) {
            uint32_t ah[4][4], al[4][4], bh[4][2], bl[4][2];
            #pragma unroll
            for (int mi = 0; mi < 4; ++mi) {
                int base = (wm * 64 + mi * 16 + g) * HTSTR + ks * 8 + t;
                ah[mi][0] = sAh32[base];
                ah[mi][1] = sAh32[base + 8 * HTSTR];
                ah[mi][2] = sAh32[base + 4];
                ah[mi][3] = sAh32[base + 8 * HTSTR + 4];
                al[mi][0] = sAl32[base];
                al[mi][1] = sAl32[base + 8 * HTSTR];
                al[mi][2] = sAl32[base + 4];
                al[mi][3] = sAl32[base + 8 * HTSTR + 4];
            }
            #pragma unroll
            for (int ni = 0; ni < 4; ++ni) {
                int base = (wn * 32 + ni * 8 + g) * HTSTR + ks * 8 + t;
                bh[ni][0] = sBh32[base]; bh[ni][1] = sBh32[base + 4];
                bl[ni][0] = sBl32[base]; bl[ni][1] = sBl32[base + 4];
            }
            #pragma unroll
            for (int mi = 0; mi < 4; ++mi)
                #pragma unroll
                for (int ni = 0; ni < 4; ++ni) {
                    MMA(acc[mi][ni], ah[mi], bh[ni]);
                    MMA(acc[mi][ni], ah[mi], bl[ni]);
                    MMA(acc[mi][ni], al[mi], bh[ni]);
                }
        }
        __syncthreads();
    }
    #pragma unroll
    for (int mi = 0; mi < 4; ++mi)
        #pragma unroll
        for (int ni = 0; ni < 4; ++ni) {
            int row = bm + wm * 64 + mi * 16 + g;
            int col = bn + wn * 32 + ni * 8 + 2 * t;
            *(float2*)(Cm + (size_t)row * LDC + col)       = make_float2(acc[mi][ni][0], acc[mi][ni][1]);
            *(float2*)(Cm + (size_t)(row + 8) * LDC + col) = make_float2(acc[mi][ni][2], acc[mi][ni][3]);
        }
}

// ---------------- K3: S[q,l] = 9-tap diagonal stencil of D / norm[l] ------
__global__ void k_score() {
    int i = blockIdx.z;
    int idx = blockIdx.x * 256 + threadIdx.x;
    int q = idx >> 12, l = idx & 4095;
    int x = q >> 6, y = q & 63, u = l >> 6, v = l & 63;
    const float* D = g_D[i];
    float s = 0.f;
    #pragma unroll
    for (int a = -1; a <= 1; ++a) {
        if ((unsigned)(x + a) < 64u && (unsigned)(u + a) < 64u) {
            #pragma unroll
            for (int bo = -1; bo <= 1; ++bo) {
                if ((unsigned)(y + bo) < 64u && (unsigned)(v + bo) < 64u) {
                    int off = a * 64 + bo;
                    s += D[(size_t)(q + off) * 4096 + (l + off)];
                }
            }
        }
    }
    g_S[i][(size_t)q * 4096 + l] = s / g_norm[i][l];
}

// ---------------- K4: fuse pass 1 (flat diag, S -> F1 in g_D) --------------
__global__ void k_fuse1() {
    int i = blockIdx.z;
    int idx = blockIdx.x * 256 + threadIdx.x;
    int p = idx >> 12, q = idx & 4095;
    const float* S = g_S[i];
    float s = 0.f;
    #pragma unroll
    for (int d = -1; d <= 1; ++d) {
        int pp = p + d, qq = q + d;
        if ((unsigned)pp < 4096u && (unsigned)qq < 4096u) s += S[(size_t)pp * 4096 + qq];
    }
    g_D[i][(size_t)p * 4096 + q] = s;
}

// -------- K5: fused fuse2 + masked softmax, output AT (transposed coords) --
// AT[pt, qt] = softmax_row( sum_d F1[T(pt+d), T(qt+d)] ) with mask mmT.
// T(z) = (z&63)*64 + (z>>6). Rows loaded contiguous; column permutation via
// padded smem: store F1[r,c] at (c&63)*65 + (c>>6); lookup T(z) at (z>>6)*65+(z&63).
__global__ void k_fuse2sm() {
    extern __shared__ float smf[];     // 3 * 4160 floats
    __shared__ float red[256];
    int i = blockIdx.z, pt = blockIdx.x, tid = threadIdx.x;
    const float* F1 = g_D[i];

    #pragma unroll
    for (int d = 0; d < 3; ++d) {
        int pz = pt + d - 1;
        float* dst = smf + d * 4160;
        if ((unsigned)pz < 4096u) {
            int rd = ((pz & 63) << 6) | (pz >> 6);
            const float* row = F1 + (size_t)rd * 4096;
            #pragma unroll
            for (int j = 0; j < 16; ++j) {
                int c = tid + j * 256;
                dst[(c & 63) * 65 + (c >> 6)] = row[c];
            }
        } else {
            #pragma unroll
            for (int j = 0; j < 16; ++j) {
                int c = tid + j * 256;
                dst[(c & 63) * 65 + (c >> 6)] = 0.f;
            }
        }
    }
    __syncthreads();

    float vals[16], msk[16];
    float mx = -3.4e38f;
    #pragma unroll
    for (int j = 0; j < 16; ++j) {
        int qt = tid + j * 256;
        float s = 0.f;
        #pragma unroll
        for (int d = 0; d < 3; ++d) {
            int z = qt + d - 1;
            if ((unsigned)z < 4096u)
                s += smf[d * 4160 + (z >> 6) * 65 + (z & 63)];
        }
        float m = g_mmT[qt];
        msk[j] = m;
        float v = s * m * 10.0f;
        vals[j] = v;
        mx = fmaxf(mx, v);
    }
    red[tid] = mx; __syncthreads();
    #pragma unroll
    for (int s = 128; s > 0; s >>= 1) { if (tid < s) red[tid] = fmaxf(red[tid], red[tid + s]); __syncthreads(); }
    mx = red[0]; __syncthreads();
    float sum = 0.f;
    #pragma unroll
    for (int j = 0; j < 16; ++j) { vals[j] = expf(vals[j] - mx); sum += vals[j]; }
    red[tid] = sum; __syncthreads();
    #pragma unroll
    for (int s = 128; s > 0; s >>= 1) { if (tid < s) red[tid] += red[tid + s]; __syncthreads(); }
    float inv = 1.0f / red[0];
    float* out = g_S[i] + (size_t)pt * 4096;
    #pragma unroll
    for (int j = 0; j < 16; ++j) {
        int qt = tid + j * 256;
        out[qt] = vals[j] * inv * msk[j];
    }
}

// ------ K7: build A-tilde (primed ordering, reads AT coalesced) -------------
// q0' = y0*65+x0, lp' = vp*65+up.
__global__ void k_Abuild() {
    int i = blockIdx.z;
    int q0p = blockIdx.y;                      // 0..4224
    int lpp = blockIdx.x * 256 + threadIdx.x;  // 0..4351
    int y0 = q0p / 65, x0 = q0p % 65;
    int vp = lpp / 65, up = lpp % 65;
    const float* AT = g_S[i];
    float s = 0.f;
    #pragma unroll
    for (int a = 0; a < 2; ++a) {
        int xr = x0 - a, ur = up - a;
        if ((unsigned)xr < 64u && (unsigned)ur < 64u) {
            #pragma unroll
            for (int bo = 0; bo < 2; ++bo) {
                int yr = y0 - bo, vr = vp - bo;
                if ((unsigned)yr < 64u && (unsigned)vr < 64u)
                    s += AT[(size_t)(yr * 64 + xr) * 4096 + (vr * 64 + ur)];
            }
        }
    }
    __nv_bfloat16 h, l;
    split_bf16(s, h, l);
    g_Ath[i][(size_t)q0p * MQP + lpp] = h;
    g_Atl[i][(size_t)q0p * MQP + lpp] = l;
}

// ------ K8: build Bt[n][lp'] (bf16 hi/lo, primed K ordering) ----------------
__global__ void k_Btbuild(const float* __restrict__ b) {
    int i = blockIdx.z;
    int n = blockIdx.y;
    int lpp = blockIdx.x * 256 + threadIdx.x;
    int par = n / IC, c = n - par * IC;
    int rx = par >> 1, ry = par & 1;
    int vp = lpp / 65, up = lpp % 65;
    int X = 2 * up + rx - 1, Y = 2 * vp + ry - 1;
    float val = 0.f;
    if (lpp < MQ && (unsigned)X < 128u && (unsigned)Y < 128u)
        val = b[(((size_t)i * IH + X) * IW + Y) * IC + c];
    __nv_bfloat16 h, l;
    split_bf16(val, h, l);
    g_Bth[i][(size_t)n * MQP + lpp] = h;
    g_Btl[i][(size_t)n * MQP + lpp] = l;
}

// ---------------- K10: final parity gather -> output (primed rows) ----------
__global__ void k_output(float* __restrict__ out) {
    int i = blockIdx.z;
    int idx = blockIdx.x * 256 + threadIdx.x;
    int c = idx % IC;
    int rest = idx / IC;
    int Y = rest % IW, X = rest / IW;
    int rx = (X + 1) & 1, ry = (Y + 1) & 1;
    int x0 = (X + 1 - rx) >> 1, y0 = (Y + 1 - ry) >> 1;
    float v = g_On[i][(size_t)(y0 * 65 + x0) * NOUT + ((rx << 1) | ry) * IC + c];
    out[(size_t)i * (IH * IW * IC) + idx] = 0.25f * v;
}

// ---------------- launch -----------------------------------------------------
extern "C" void kernel_launch(void* const* d_in, const int* in_sizes, int n_in,
                              void* d_out, int out_size) {
    const float* f    = (const float*)d_in[0];
    const float* b    = (const float*)d_in[1];
    const float* mask = (const float*)d_in[2];
    float* out = (float*)d_out;

    const int gemm_smem = 8 * TILEB * 2;      // 81920 B
    const int f2_smem   = 3 * 4160 * 4;       // 49920 B
    cudaFuncSetAttribute(k_gemm_mma<0>, cudaFuncAttributeMaxDynamicSharedMemorySize, gemm_smem);
    cudaFuncSetAttribute(k_gemm_mma<1>, cudaFuncAttributeMaxDynamicSharedMemorySize, gemm_smem);
    cudaFuncSetAttribute(k_fuse2sm, cudaFuncAttributeMaxDynamicSharedMemorySize, f2_smem);

    k_pack    <<<dim3(4096, 1, NB), 192>>>(f, b);
    k_norm_mm <<<dim3(32,   1, NB), 128>>>(mask);
    k_gemm_mma<0><<<dim3(32, 32, NB), 256, gemm_smem>>>();
    k_score   <<<dim3(65536, 1, NB), 256>>>();
    k_fuse1   <<<dim3(65536, 1, NB), 256>>>();
    k_fuse2sm <<<dim3(4096, 1, NB), 256, f2_smem>>>();
    k_Abuild  <<<dim3(17, MQ, NB), 256>>>();
    k_Btbuild <<<dim3(17, NOUT, NB), 256>>>(b);
    k_gemm_mma<1><<<dim3(6, 34, NB), 256, gemm_smem>>>();
    k_output  <<<dim3(12288, 1, NB), 256>>>(out);
}

// round 7
// speedup vs baseline: 2.1777x; 1.0826x over previous
#include <cuda_runtime.h>
#include <cuda_bf16.h>
#include <math.h>
#include <stdint.h>

#define NB   2
#define IH   128
#define IW   128
#define IC   192
#define LTOT 4096
#define MQ   4225   // 65*65
#define MQP  4352   // 34*128
#define NOUT 768
#define KD   192

// ---------------- scratch ----------------
__device__ __nv_bfloat16 g_fdh[NB][LTOT][KD], g_fdl[NB][LTOT][KD];
__device__ __nv_bfloat16 g_bdh[NB][LTOT][KD], g_bdl[NB][LTOT][KD];
__device__ float g_n2[NB][LTOT];
__device__ float g_norm[NB][LTOT];
__device__ float g_mmT[LTOT];                       // mask, transposed index
__device__ float g_D[NB][(size_t)LTOT * LTOT];      // D, then F1
__device__ float g_S[NB][(size_t)LTOT * LTOT];      // S, then AT (attention, transposed)
__device__ __nv_bfloat16 g_Ath[NB][(size_t)MQP * MQP];
__device__ __nv_bfloat16 g_Atl[NB][(size_t)MQP * MQP];
__device__ __nv_bfloat16 g_Bth[NB][(size_t)NOUT * MQP];
__device__ __nv_bfloat16 g_Btl[NB][(size_t)NOUT * MQP];
__device__ float g_On[NB][(size_t)MQP * NOUT];

__device__ __forceinline__ void split_bf16(float v, __nv_bfloat16& h, __nv_bfloat16& l) {
    h = __float2bfloat16(v);
    l = __float2bfloat16(v - __bfloat162float(h));
}
__device__ __forceinline__ uint32_t smem_u32(const void* p) {
    uint32_t a;
    asm("{ .reg .u64 t; cvta.to.shared.u64 t, %1; cvt.u32.u64 %0, t; }" : "=r"(a) : "l"(p));
    return a;
}

#define MMA(ac, a, bb) \
    asm volatile("mma.sync.aligned.m16n8k16.row.col.f32.bf16.bf16.f32 " \
        "{%0,%1,%2,%3}, {%4,%5,%6,%7}, {%8,%9}, {%0,%1,%2,%3};" \
        : "+f"((ac)[0]), "+f"((ac)[1]), "+f"((ac)[2]), "+f"((ac)[3]) \
        : "r"((a)[0]), "r"((a)[1]), "r"((a)[2]), "r"((a)[3]), \
          "r"((bb)[0]), "r"((bb)[1]))

// ---------------- K1: downsample + pack bf16 hi/lo + |bd|^2 ---------------
__global__ void k_pack(const float* __restrict__ f, const float* __restrict__ b) {
    int i = blockIdx.z, p = blockIdx.x;
    int x = p >> 6, y = p & 63;
    size_t base = (((size_t)i * IH + 2 * x) * IW + 2 * y) * IC;
    int c = threadIdx.x;
    float fv = f[base + c], bv = b[base + c];
    __nv_bfloat16 h, l;
    split_bf16(fv, h, l); g_fdh[i][p][c] = h; g_fdl[i][p][c] = l;
    split_bf16(bv, h, l); g_bdh[i][p][c] = h; g_bdl[i][p][c] = l;

    __shared__ float sh[192];
    sh[c] = bv * bv;
    __syncthreads();
    if (c < 64) sh[c] += sh[c + 64] + sh[c + 128];
    __syncthreads();
    if (c < 32) {
        float v = sh[c] + sh[c + 32];
        #pragma unroll
        for (int o = 16; o > 0; o >>= 1) v += __shfl_down_sync(0xffffffffu, v, o);
        if (c == 0) g_n2[i][p] = v;
    }
}

// ---------------- K1b: patch norms + transposed mask ------------------------
__global__ void k_norm_mm(const float* __restrict__ mask) {
    int i = blockIdx.z;
    int l = blockIdx.x * 128 + threadIdx.x;
    int u = l >> 6, v = l & 63;
    float s = 0.f;
    #pragma unroll
    for (int a = -1; a <= 1; ++a)
        #pragma unroll
        for (int bo = -1; bo <= 1; ++bo) {
            int uu = u + a, vv = v + bo;
            if ((unsigned)uu < 64u && (unsigned)vv < 64u) s += g_n2[i][uu * 64 + vv];
        }
    g_norm[i][l] = fmaxf(sqrtf(s), 1e-4f);
    if (i == 0) {
        float ms = 0.f;
        #pragma unroll
        for (int a = -1; a <= 1; ++a)
            #pragma unroll
            for (int bo = -1; bo <= 1; ++bo) {
                int uu = u + a, vv = v + bo;
                if ((unsigned)uu < 64u && (unsigned)vv < 64u) ms += mask[(2 * uu) * IW + 2 * vv];
            }
        g_mmT[((l & 63) << 6) | (l >> 6)] = (ms == 0.0f) ? 1.0f : 0.0f;
    }
}

// ---- split-bf16 HMMA GEMM, cp.async 3-stage pipelined ----------------------
#define TSTR 40
#define TILEB (128 * TSTR)

__device__ __forceinline__ void cp_tile(const __nv_bfloat16* __restrict__ src,
                                        int ld, int row0, int k0,
                                        __nv_bfloat16* dst, int tid) {
    #pragma unroll
    for (int j = 0; j < 2; ++j) {
        int idx = j * 256 + tid;
        int r = idx >> 2, cc = idx & 3;
        uint32_t d = smem_u32(dst + r * TSTR + cc * 8);
        const void* s = src + (size_t)(row0 + r) * ld + k0 + cc * 8;
        asm volatile("cp.async.ca.shared.global [%0], [%1], 16;" :: "r"(d), "l"(s));
    }
}

template<int MODE>
__global__ __launch_bounds__(256) void k_gemm_mma() {
    constexpr int KIT = (MODE == 0) ? 6 : 136;
    constexpr int LDA = (MODE == 0) ? KD : MQP;
    constexpr int LDC = (MODE == 0) ? 4096 : NOUT;
    extern __shared__ __nv_bfloat16 smg[];   // 3 stages * 4 tiles * TILEB

    int i = blockIdx.z, tid = threadIdx.x;
    int wid = tid >> 5, lane = tid & 31;
    int wm = wid & 1, wn = wid >> 1;
    int g = lane >> 2, t = lane & 3;
    int bm = blockIdx.y << 7, bn = blockIdx.x << 7;

    const __nv_bfloat16 *Ah, *Al, *Bh, *Bl;
    float* Cm;
    if (MODE == 0) {
        Ah = &g_fdh[i][0][0]; Al = &g_fdl[i][0][0];
        Bh = &g_bdh[i][0][0]; Bl = &g_bdl[i][0][0]; Cm = g_D[i];
    } else {
        Ah = g_Ath[i]; Al = g_Atl[i];
        Bh = g_Bth[i]; Bl = g_Btl[i]; Cm = g_On[i];
    }

    float acc[4][4][4] = {};
    const int HTSTR = TSTR / 2;

    // prologue: stages 0,1
    #pragma unroll
    for (int s = 0; s < 2; ++s) {
        __nv_bfloat16* b0 = smg + s * 4 * TILEB;
        int k0 = s << 5;
        cp_tile(Ah, LDA, bm, k0, b0, tid);
        cp_tile(Al, LDA, bm, k0, b0 + TILEB, tid);
        cp_tile(Bh, LDA, bn, k0, b0 + 2 * TILEB, tid);
        cp_tile(Bl, LDA, bn, k0, b0 + 3 * TILEB, tid);
        asm volatile("cp.async.commit_group;" ::: "memory");
    }

    for (int it = 0; it < KIT; ++it) {
        if (it + 1 < KIT) asm volatile("cp.async.wait_group 1;" ::: "memory");
        else              asm volatile("cp.async.wait_group 0;" ::: "memory");
        __syncthreads();
        int st = it % 3;
        const uint32_t* sAh32 = (const uint32_t*)(smg + st * 4 * TILEB);
        const uint32_t* sAl32 = sAh32 + TILEB / 2;
        const uint32_t* sBh32 = sAh32 + TILEB;
        const uint32_t* sBl32 = sAh32 + 3 * TILEB / 2;
        #pragma unroll
        for (int ks = 0; ks < 2; ++ks) {
            uint32_t ah[4][4], al[4][4], bh[4][2], bl[4][2];
            #pragma unroll
            for (int mi = 0; mi < 4; ++mi) {
                int base = (wm * 64 + mi * 16 + g) * HTSTR + ks * 8 + t;
                ah[mi][0] = sAh32[base];
                ah[mi][1] = sAh32[base + 8 * HTSTR];
                ah[mi][2] = sAh32[base + 4];
                ah[mi][3] = sAh32[base + 8 * HTSTR + 4];
                al[mi][0] = sAl32[base];
                al[mi][1] = sAl32[base + 8 * HTSTR];
                al[mi][2] = sAl32[base + 4];
                al[mi][3] = sAl32[base + 8 * HTSTR + 4];
            }
            #pragma unroll
            for (int ni = 0; ni < 4; ++ni) {
                int base = (wn * 32 + ni * 8 + g) * HTSTR + ks * 8 + t;
                bh[ni][0] = sBh32[base]; bh[ni][1] = sBh32[base + 4];
                bl[ni][0] = sBl32[base]; bl[ni][1] = sBl32[base + 4];
            }
            #pragma unroll
            for (int mi = 0; mi < 4; ++mi)
                #pragma unroll
                for (int ni = 0; ni < 4; ++ni) {
                    MMA(acc[mi][ni], ah[mi], bh[ni]);
                    MMA(acc[mi][ni], ah[mi], bl[ni]);
                    MMA(acc[mi][ni], al[mi], bh[ni]);
                }
        }
        if (it + 2 < KIT) {
            __nv_bfloat16* b0 = smg + ((it + 2) % 3) * 4 * TILEB;
            int k0 = (it + 2) << 5;
            cp_tile(Ah, LDA, bm, k0, b0, tid);
            cp_tile(Al, LDA, bm, k0, b0 + TILEB, tid);
            cp_tile(Bh, LDA, bn, k0, b0 + 2 * TILEB, tid);
            cp_tile(Bl, LDA, bn, k0, b0 + 3 * TILEB, tid);
            asm volatile("cp.async.commit_group;" ::: "memory");
        }
    }
    #pragma unroll
    for (int mi = 0; mi < 4; ++mi)
        #pragma unroll
        for (int ni = 0; ni < 4; ++ni) {
            int row = bm + wm * 64 + mi * 16 + g;
            int col = bn + wn * 32 + ni * 8 + 2 * t;
            *(float2*)(Cm + (size_t)row * LDC + col)       = make_float2(acc[mi][ni][0], acc[mi][ni][1]);
            *(float2*)(Cm + (size_t)(row + 8) * LDC + col) = make_float2(acc[mi][ni][2], acc[mi][ni][3]);
        }
}

// ---------------- K3: banded-smem score stencil -----------------------------
// Block computes S[q0..q0+3][0..4096). Bands a in {-1,0,1}: rows q0+a*64-1..+4.
__global__ __launch_bounds__(512) void k_score() {
    extern __shared__ float sb[];     // 6 * 4096 floats
    int i = blockIdx.z;
    int q0 = blockIdx.x << 2;
    int tid = threadIdx.x;
    int x0 = q0 >> 6, y0 = q0 & 63;
    const float* D = g_D[i];
    float acc[4][8] = {};

    #pragma unroll
    for (int a = -1; a <= 1; ++a) {
        if ((unsigned)(x0 + a) >= 64u) continue;   // block-uniform skip
        __syncthreads();
        #pragma unroll
        for (int s = 0; s < 6; ++s) {
            int row = q0 + a * 64 + s - 1;
            float4* dst = (float4*)(sb + s * 4096);
            if ((unsigned)row < 4096u) {
                const float4* src = (const float4*)(D + (size_t)row * 4096);
                dst[tid] = src[tid];
                dst[tid + 512] = src[tid + 512];
            } else {
                dst[tid] = make_float4(0.f, 0.f, 0.f, 0.f);
                dst[tid + 512] = make_float4(0.f, 0.f, 0.f, 0.f);
            }
        }
        __syncthreads();
        #pragma unroll
        for (int k = 0; k < 8; ++k) {
            int l = tid + (k << 9);
            int u = l >> 6, v = l & 63;
            if ((unsigned)(u + a) >= 64u) continue;
            #pragma unroll
            for (int b = -1; b <= 1; ++b) {
                if ((unsigned)(v + b) >= 64u) continue;
                int col = l + a * 64 + b;
                #pragma unroll
                for (int qi = 0; qi < 4; ++qi) {
                    if ((unsigned)(y0 + qi + b) < 64u)
                        acc[qi][k] += sb[(qi + b + 1) * 4096 + col];
                }
            }
        }
    }
    const float* nm = g_norm[i];
    float* S = g_S[i] + (size_t)q0 * 4096;
    #pragma unroll
    for (int k = 0; k < 8; ++k) {
        int l = tid + (k << 9);
        float inv = 1.0f / nm[l];
        #pragma unroll
        for (int qi = 0; qi < 4; ++qi)
            S[(size_t)qi * 4096 + l] = acc[qi][k] * inv;
    }
}

// ---------------- K4: fuse pass 1 (smem rows, S -> F1 in g_D) ---------------
__global__ __launch_bounds__(512) void k_fuse1() {
    extern __shared__ float sb[];     // 6 * 4096 floats
    int i = blockIdx.z;
    int p0 = blockIdx.x << 2;
    int tid = threadIdx.x;
    const float* S = g_S[i];
    #pragma unroll
    for (int s = 0; s < 6; ++s) {
        int row = p0 + s - 1;
        float4* dst = (float4*)(sb + s * 4096);
        if ((unsigned)row < 4096u) {
            const float4* src = (const float4*)(S + (size_t)row * 4096);
            dst[tid] = src[tid];
            dst[tid + 512] = src[tid + 512];
        } else {
            dst[tid] = make_float4(0.f, 0.f, 0.f, 0.f);
            dst[tid + 512] = make_float4(0.f, 0.f, 0.f, 0.f);
        }
    }
    __syncthreads();
    float* F1 = g_D[i] + (size_t)p0 * 4096;
    #pragma unroll
    for (int k = 0; k < 8; ++k) {
        int q = tid + (k << 9);
        #pragma unroll
        for (int qi = 0; qi < 4; ++qi) {
            float s = 0.f;
            #pragma unroll
            for (int d = -1; d <= 1; ++d) {
                int qq = q + d;
                if ((unsigned)qq < 4096u)
                    s += sb[(qi + d + 1) * 4096 + qq];
            }
            F1[(size_t)qi * 4096 + q] = s;
        }
    }
}

// -------- K5: fused fuse2 + masked softmax, output AT (transposed coords) --
__global__ void k_fuse2sm() {
    extern __shared__ float smf[];     // 3 * 4160 floats
    __shared__ float red[256];
    int i = blockIdx.z, pt = blockIdx.x, tid = threadIdx.x;
    const float* F1 = g_D[i];

    #pragma unroll
    for (int d = 0; d < 3; ++d) {
        int pz = pt + d - 1;
        float* dst = smf + d * 4160;
        if ((unsigned)pz < 4096u) {
            int rd = ((pz & 63) << 6) | (pz >> 6);
            const float* row = F1 + (size_t)rd * 4096;
            #pragma unroll
            for (int j = 0; j < 16; ++j) {
                int c = tid + j * 256;
                dst[(c & 63) * 65 + (c >> 6)] = row[c];
            }
        } else {
            #pragma unroll
            for (int j = 0; j < 16; ++j) {
                int c = tid + j * 256;
                dst[(c & 63) * 65 + (c >> 6)] = 0.f;
            }
        }
    }
    __syncthreads();

    float vals[16], msk[16];
    float mx = -3.4e38f;
    #pragma unroll
    for (int j = 0; j < 16; ++j) {
        int qt = tid + j * 256;
        float s = 0.f;
        #pragma unroll
        for (int d = 0; d < 3; ++d) {
            int z = qt + d - 1;
            if ((unsigned)z < 4096u)
                s += smf[d * 4160 + (z >> 6) * 65 + (z & 63)];
        }
        float m = g_mmT[qt];
        msk[j] = m;
        float v = s * m * 10.0f;
        vals[j] = v;
        mx = fmaxf(mx, v);
    }
    red[tid] = mx; __syncthreads();
    #pragma unroll
    for (int s = 128; s > 0; s >>= 1) { if (tid < s) red[tid] = fmaxf(red[tid], red[tid + s]); __syncthreads(); }
    mx = red[0]; __syncthreads();
    float sum = 0.f;
    #pragma unroll
    for (int j = 0; j < 16; ++j) { vals[j] = expf(vals[j] - mx); sum += vals[j]; }
    red[tid] = sum; __syncthreads();
    #pragma unroll
    for (int s = 128; s > 0; s >>= 1) { if (tid < s) red[tid] += red[tid + s]; __syncthreads(); }
    float inv = 1.0f / red[0];
    float* out = g_S[i] + (size_t)pt * 4096;
    #pragma unroll
    for (int j = 0; j < 16; ++j) {
        int qt = tid + j * 256;
        out[qt] = vals[j] * inv * msk[j];
    }
}

// ------ K7: build A-tilde (primed ordering, reads AT coalesced) -------------
__global__ void k_Abuild() {
    int i = blockIdx.z;
    int q0p = blockIdx.y;
    int lpp = blockIdx.x * 256 + threadIdx.x;
    int y0 = q0p / 65, x0 = q0p % 65;
    int vp = lpp / 65, up = lpp % 65;
    const float* AT = g_S[i];
    float s = 0.f;
    #pragma unroll
    for (int a = 0; a < 2; ++a) {
        int xr = x0 - a, ur = up - a;
        if ((unsigned)xr < 64u && (unsigned)ur < 64u) {
            #pragma unroll
            for (int bo = 0; bo < 2; ++bo) {
                int yr = y0 - bo, vr = vp - bo;
                if ((unsigned)yr < 64u && (unsigned)vr < 64u)
                    s += AT[(size_t)(yr * 64 + xr) * 4096 + (vr * 64 + ur)];
            }
        }
    }
    __nv_bfloat16 h, l;
    split_bf16(s, h, l);
    g_Ath[i][(size_t)q0p * MQP + lpp] = h;
    g_Atl[i][(size_t)q0p * MQP + lpp] = l;
}

// ------ K8: build Bt[n][lp'] (bf16 hi/lo, primed K ordering) ----------------
__global__ void k_Btbuild(const float* __restrict__ b) {
    int i = blockIdx.z;
    int n = blockIdx.y;
    int lpp = blockIdx.x * 256 + threadIdx.x;
    int par = n / IC, c = n - par * IC;
    int rx = par >> 1, ry = par & 1;
    int vp = lpp / 65, up = lpp % 65;
    int X = 2 * up + rx - 1, Y = 2 * vp + ry - 1;
    float val = 0.f;
    if (lpp < MQ && (unsigned)X < 128u && (unsigned)Y < 128u)
        val = b[(((size_t)i * IH + X) * IW + Y) * IC + c];
    __nv_bfloat16 h, l;
    split_bf16(val, h, l);
    g_Bth[i][(size_t)n * MQP + lpp] = h;
    g_Btl[i][(size_t)n * MQP + lpp] = l;
}

// ---------------- K10: final parity gather -> output (primed rows) ----------
__global__ void k_output(float* __restrict__ out) {
    int i = blockIdx.z;
    int idx = blockIdx.x * 256 + threadIdx.x;
    int c = idx % IC;
    int rest = idx / IC;
    int Y = rest % IW, X = rest / IW;
    int rx = (X + 1) & 1, ry = (Y + 1) & 1;
    int x0 = (X + 1 - rx) >> 1, y0 = (Y + 1 - ry) >> 1;
    float v = g_On[i][(size_t)(y0 * 65 + x0) * NOUT + ((rx << 1) | ry) * IC + c];
    out[(size_t)i * (IH * IW * IC) + idx] = 0.25f * v;
}

// ---------------- launch -----------------------------------------------------
extern "C" void kernel_launch(void* const* d_in, const int* in_sizes, int n_in,
                              void* d_out, int out_size) {
    const float* f    = (const float*)d_in[0];
    const float* b    = (const float*)d_in[1];
    const float* mask = (const float*)d_in[2];
    float* out = (float*)d_out;

    const int gemm_smem = 8 * TILEB * 3;      // 122880 B (3 stages)
    const int f2_smem   = 3 * 4160 * 4;       // 49920 B
    const int band_smem = 6 * 4096 * 4;       // 98304 B
    cudaFuncSetAttribute(k_gemm_mma<0>, cudaFuncAttributeMaxDynamicSharedMemorySize, gemm_smem);
    cudaFuncSetAttribute(k_gemm_mma<1>, cudaFuncAttributeMaxDynamicSharedMemorySize, gemm_smem);
    cudaFuncSetAttribute(k_fuse2sm, cudaFuncAttributeMaxDynamicSharedMemorySize, f2_smem);
    cudaFuncSetAttribute(k_score,  cudaFuncAttributeMaxDynamicSharedMemorySize, band_smem);
    cudaFuncSetAttribute(k_fuse1,  cudaFuncAttributeMaxDynamicSharedMemorySize, band_smem);

    k_pack    <<<dim3(4096, 1, NB), 192>>>(f, b);
    k_norm_mm <<<dim3(32,   1, NB), 128>>>(mask);
    k_gemm_mma<0><<<dim3(32, 32, NB), 256, gemm_smem>>>();
    k_score   <<<dim3(1024, 1, NB), 512, band_smem>>>();
    k_fuse1   <<<dim3(1024, 1, NB), 512, band_smem>>>();
    k_fuse2sm <<<dim3(4096, 1, NB), 256, f2_smem>>>();
    k_Abuild  <<<dim3(17, MQ, NB), 256>>>();
    k_Btbuild <<<dim3(17, NOUT, NB), 256>>>(b);
    k_gemm_mma<1><<<dim3(6, 34, NB), 256, gemm_smem>>>();
    k_output  <<<dim3(12288, 1, NB), 256>>>(out);
}

// round 8
// speedup vs baseline: 2.4075x; 1.1055x over previous
#include <cuda_runtime.h>
#include <cuda_bf16.h>
#include <math.h>
#include <stdint.h>

#define NB   2
#define IH   128
#define IW   128
#define IC   192
#define LTOT 4096
#define MQ   4225   // 65*65
#define MQP  4352   // 34*128
#define NOUT 768
#define KD   192

// ---------------- scratch ----------------
__device__ __nv_bfloat16 g_fdh[NB][LTOT][KD], g_fdl[NB][LTOT][KD];
__device__ __nv_bfloat16 g_bdh[NB][LTOT][KD], g_bdl[NB][LTOT][KD];
__device__ float g_n2[NB][LTOT];
__device__ float g_norm[NB][LTOT];
__device__ float g_mmT[LTOT];                       // mask, transposed index
__device__ float g_D[NB][(size_t)LTOT * LTOT];      // D, then F1
__device__ float g_S[NB][(size_t)LTOT * LTOT];      // S, then AT (attention, transposed)
__device__ __nv_bfloat16 g_Ath[NB][(size_t)MQP * MQP];
__device__ __nv_bfloat16 g_Atl[NB][(size_t)MQP * MQP];
__device__ __nv_bfloat16 g_Bth[NB][(size_t)NOUT * MQP];
__device__ __nv_bfloat16 g_Btl[NB][(size_t)NOUT * MQP];

__device__ __forceinline__ void split_bf16(float v, __nv_bfloat16& h, __nv_bfloat16& l) {
    h = __float2bfloat16(v);
    l = __float2bfloat16(v - __bfloat162float(h));
}
__device__ __forceinline__ uint32_t smem_u32(const void* p) {
    uint32_t a;
    asm("{ .reg .u64 t; cvta.to.shared.u64 t, %1; cvt.u32.u64 %0, t; }" : "=r"(a) : "l"(p));
    return a;
}

#define MMA(ac, a, bb) \
    asm volatile("mma.sync.aligned.m16n8k16.row.col.f32.bf16.bf16.f32 " \
        "{%0,%1,%2,%3}, {%4,%5,%6,%7}, {%8,%9}, {%0,%1,%2,%3};" \
        : "+f"((ac)[0]), "+f"((ac)[1]), "+f"((ac)[2]), "+f"((ac)[3]) \
        : "r"((a)[0]), "r"((a)[1]), "r"((a)[2]), "r"((a)[3]), \
          "r"((bb)[0]), "r"((bb)[1]))

#define LDSM4(r0, r1, r2, r3, addr) \
    asm volatile("ldmatrix.sync.aligned.m8n8.x4.shared.b16 {%0,%1,%2,%3}, [%4];" \
        : "=r"(r0), "=r"(r1), "=r"(r2), "=r"(r3) : "r"(addr))

// ---------------- K1: downsample + pack bf16 hi/lo + |bd|^2 ---------------
__global__ void k_pack(const float* __restrict__ f, const float* __restrict__ b) {
    int i = blockIdx.z, p = blockIdx.x;
    int x = p >> 6, y = p & 63;
    size_t base = (((size_t)i * IH + 2 * x) * IW + 2 * y) * IC;
    int c = threadIdx.x;
    float fv = f[base + c], bv = b[base + c];
    __nv_bfloat16 h, l;
    split_bf16(fv, h, l); g_fdh[i][p][c] = h; g_fdl[i][p][c] = l;
    split_bf16(bv, h, l); g_bdh[i][p][c] = h; g_bdl[i][p][c] = l;

    __shared__ float sh[192];
    sh[c] = bv * bv;
    __syncthreads();
    if (c < 64) sh[c] += sh[c + 64] + sh[c + 128];
    __syncthreads();
    if (c < 32) {
        float v = sh[c] + sh[c + 32];
        #pragma unroll
        for (int o = 16; o > 0; o >>= 1) v += __shfl_down_sync(0xffffffffu, v, o);
        if (c == 0) g_n2[i][p] = v;
    }
}

// ---------------- K1b: patch norms + transposed mask ------------------------
__global__ void k_norm_mm(const float* __restrict__ mask) {
    int i = blockIdx.z;
    int l = blockIdx.x * 128 + threadIdx.x;
    int u = l >> 6, v = l & 63;
    float s = 0.f;
    #pragma unroll
    for (int a = -1; a <= 1; ++a)
        #pragma unroll
        for (int bo = -1; bo <= 1; ++bo) {
            int uu = u + a, vv = v + bo;
            if ((unsigned)uu < 64u && (unsigned)vv < 64u) s += g_n2[i][uu * 64 + vv];
        }
    g_norm[i][l] = fmaxf(sqrtf(s), 1e-4f);
    if (i == 0) {
        float ms = 0.f;
        #pragma unroll
        for (int a = -1; a <= 1; ++a)
            #pragma unroll
            for (int bo = -1; bo <= 1; ++bo) {
                int uu = u + a, vv = v + bo;
                if ((unsigned)uu < 64u && (unsigned)vv < 64u) ms += mask[(2 * uu) * IW + 2 * vv];
            }
        g_mmT[((l & 63) << 6) | (l >> 6)] = (ms == 0.0f) ? 1.0f : 0.0f;
    }
}

// ---- split-bf16 HMMA GEMM, cp.async 3-stage pipelined, ldmatrix frags ------
#define TSTR 40
#define TILEB (128 * TSTR)

__device__ __forceinline__ void cp_tile(const __nv_bfloat16* __restrict__ src,
                                        int ld, int row0, int k0,
                                        __nv_bfloat16* dst, int tid) {
    #pragma unroll
    for (int j = 0; j < 2; ++j) {
        int idx = j * 256 + tid;
        int r = idx >> 2, cc = idx & 3;
        uint32_t d = smem_u32(dst + r * TSTR + cc * 8);
        const void* s = src + (size_t)(row0 + r) * ld + k0 + cc * 8;
        asm volatile("cp.async.ca.shared.global [%0], [%1], 16;" :: "r"(d), "l"(s));
    }
}

template<int MODE>
__global__ __launch_bounds__(256) void k_gemm_mma(float* __restrict__ outp) {
    constexpr int KIT = (MODE == 0) ? 6 : 136;
    constexpr int LDA = (MODE == 0) ? KD : MQP;
    extern __shared__ __nv_bfloat16 smg[];   // 3 stages * 4 tiles * TILEB

    int i = blockIdx.z, tid = threadIdx.x;
    int wid = tid >> 5, lane = tid & 31;
    int wm = wid & 1, wn = wid >> 1;
    int g = lane >> 2, t = lane & 3;
    int bm = blockIdx.y << 7, bn = blockIdx.x << 7;

    const __nv_bfloat16 *Ah, *Al, *Bh, *Bl;
    if (MODE == 0) {
        Ah = &g_fdh[i][0][0]; Al = &g_fdl[i][0][0];
        Bh = &g_bdh[i][0][0]; Bl = &g_bdl[i][0][0];
    } else {
        Ah = g_Ath[i]; Al = g_Atl[i];
        Bh = g_Bth[i]; Bl = g_Btl[i];
    }

    float acc[4][4][4] = {};

    // ldmatrix lane-derived offsets (half units)
    int a_row  = wm * 64 + (lane & 15);
    int a_koff = (lane >> 4) << 3;
    int b_row  = wn * 32 + (lane & 7) + ((lane >> 4) << 3);
    int b_koff = ((lane >> 3) & 1) << 3;

    // prologue: stages 0,1
    #pragma unroll
    for (int s = 0; s < 2; ++s) {
        __nv_bfloat16* b0 = smg + s * 4 * TILEB;
        int k0 = s << 5;
        cp_tile(Ah, LDA, bm, k0, b0, tid);
        cp_tile(Al, LDA, bm, k0, b0 + TILEB, tid);
        cp_tile(Bh, LDA, bn, k0, b0 + 2 * TILEB, tid);
        cp_tile(Bl, LDA, bn, k0, b0 + 3 * TILEB, tid);
        asm volatile("cp.async.commit_group;" ::: "memory");
    }

    for (int it = 0; it < KIT; ++it) {
        if (it + 1 < KIT) asm volatile("cp.async.wait_group 1;" ::: "memory");
        else              asm volatile("cp.async.wait_group 0;" ::: "memory");
        __syncthreads();
        int st = it % 3;
        uint32_t sA_h = smem_u32(smg + st * 4 * TILEB);
        uint32_t sA_l = sA_h + TILEB * 2;
        uint32_t sB_h = sA_h + 2 * TILEB * 2;
        uint32_t sB_l = sA_h + 3 * TILEB * 2;
        #pragma unroll
        for (int ks = 0; ks < 2; ++ks) {
            uint32_t ah[4][4], al[4][4], bh[4][2], bl[4][2];
            #pragma unroll
            for (int mi = 0; mi < 4; ++mi) {
                uint32_t off = 2u * ((a_row + mi * 16) * TSTR + ks * 16 + a_koff);
                LDSM4(ah[mi][0], ah[mi][1], ah[mi][2], ah[mi][3], sA_h + off);
                LDSM4(al[mi][0], al[mi][1], al[mi][2], al[mi][3], sA_l + off);
            }
            #pragma unroll
            for (int pr = 0; pr < 2; ++pr) {
                uint32_t off = 2u * ((b_row + pr * 16) * TSTR + ks * 16 + b_koff);
                LDSM4(bh[2*pr][0], bh[2*pr][1], bh[2*pr+1][0], bh[2*pr+1][1], sB_h + off);
                LDSM4(bl[2*pr][0], bl[2*pr][1], bl[2*pr+1][0], bl[2*pr+1][1], sB_l + off);
            }
            #pragma unroll
            for (int mi = 0; mi < 4; ++mi)
                #pragma unroll
                for (int ni = 0; ni < 4; ++ni) {
                    MMA(acc[mi][ni], ah[mi], bh[ni]);
                    MMA(acc[mi][ni], ah[mi], bl[ni]);
                    MMA(acc[mi][ni], al[mi], bh[ni]);
                }
        }
        if (it + 2 < KIT) {
            __nv_bfloat16* b0 = smg + ((it + 2) % 3) * 4 * TILEB;
            int k0 = (it + 2) << 5;
            cp_tile(Ah, LDA, bm, k0, b0, tid);
            cp_tile(Al, LDA, bm, k0, b0 + TILEB, tid);
            cp_tile(Bh, LDA, bn, k0, b0 + 2 * TILEB, tid);
            cp_tile(Bl, LDA, bn, k0, b0 + 3 * TILEB, tid);
            asm volatile("cp.async.commit_group;" ::: "memory");
        }
    }

    if (MODE == 0) {
        float* Cm = g_D[i];
        #pragma unroll
        for (int mi = 0; mi < 4; ++mi)
            #pragma unroll
            for (int ni = 0; ni < 4; ++ni) {
                int row = bm + wm * 64 + mi * 16 + g;
                int col = bn + wn * 32 + ni * 8 + 2 * t;
                *(float2*)(Cm + (size_t)row * 4096 + col)       = make_float2(acc[mi][ni][0], acc[mi][ni][1]);
                *(float2*)(Cm + (size_t)(row + 8) * 4096 + col) = make_float2(acc[mi][ni][2], acc[mi][ni][3]);
            }
    } else {
        // fused parity-scatter epilogue: C[row, col] -> out[X, Y, c] * 0.25
        #pragma unroll
        for (int mi = 0; mi < 4; ++mi)
            #pragma unroll
            for (int ni = 0; ni < 4; ++ni) {
                int row0 = bm + wm * 64 + mi * 16 + g;
                int col = bn + wn * 32 + ni * 8 + 2 * t;
                int par = col / IC, c = col - par * IC;
                int rx = par >> 1, ry = par & 1;
                #pragma unroll
                for (int h2 = 0; h2 < 2; ++h2) {
                    int row = row0 + 8 * h2;
                    if (row < MQ) {
                        int y0 = row / 65, x0 = row - y0 * 65;
                        int X = 2 * x0 + rx - 1, Y = 2 * y0 + ry - 1;
                        if ((unsigned)X < 128u && (unsigned)Y < 128u) {
                            float2 v = make_float2(0.25f * acc[mi][ni][2 * h2],
                                                   0.25f * acc[mi][ni][2 * h2 + 1]);
                            *(float2*)(outp + (((size_t)i * IH + X) * IW + Y) * IC + c) = v;
                        }
                    }
                }
            }
    }
}

// ---------------- K3: banded-smem score stencil -----------------------------
__global__ __launch_bounds__(512) void k_score() {
    extern __shared__ float sb[];     // 6 * 4096 floats
    int i = blockIdx.z;
    int q0 = blockIdx.x << 2;
    int tid = threadIdx.x;
    int x0 = q0 >> 6, y0 = q0 & 63;
    const float* D = g_D[i];
    float acc[4][8] = {};

    #pragma unroll
    for (int a = -1; a <= 1; ++a) {
        if ((unsigned)(x0 + a) >= 64u) continue;
        __syncthreads();
        #pragma unroll
        for (int s = 0; s < 6; ++s) {
            int row = q0 + a * 64 + s - 1;
            float4* dst = (float4*)(sb + s * 4096);
            if ((unsigned)row < 4096u) {
                const float4* src = (const float4*)(D + (size_t)row * 4096);
                dst[tid] = src[tid];
                dst[tid + 512] = src[tid + 512];
            } else {
                dst[tid] = make_float4(0.f, 0.f, 0.f, 0.f);
                dst[tid + 512] = make_float4(0.f, 0.f, 0.f, 0.f);
            }
        }
        __syncthreads();
        #pragma unroll
        for (int k = 0; k < 8; ++k) {
            int l = tid + (k << 9);
            int u = l >> 6, v = l & 63;
            if ((unsigned)(u + a) >= 64u) continue;
            #pragma unroll
            for (int b = -1; b <= 1; ++b) {
                if ((unsigned)(v + b) >= 64u) continue;
                int col = l + a * 64 + b;
                #pragma unroll
                for (int qi = 0; qi < 4; ++qi) {
                    if ((unsigned)(y0 + qi + b) < 64u)
                        acc[qi][k] += sb[(qi + b + 1) * 4096 + col];
                }
            }
        }
    }
    const float* nm = g_norm[i];
    float* S = g_S[i] + (size_t)q0 * 4096;
    #pragma unroll
    for (int k = 0; k < 8; ++k) {
        int l = tid + (k << 9);
        float inv = 1.0f / nm[l];
        #pragma unroll
        for (int qi = 0; qi < 4; ++qi)
            S[(size_t)qi * 4096 + l] = acc[qi][k] * inv;
    }
}

// ---------------- K4: fuse pass 1 (smem rows, S -> F1 in g_D) ---------------
__global__ __launch_bounds__(512) void k_fuse1() {
    extern __shared__ float sb[];     // 6 * 4096 floats
    int i = blockIdx.z;
    int p0 = blockIdx.x << 2;
    int tid = threadIdx.x;
    const float* S = g_S[i];
    #pragma unroll
    for (int s = 0; s < 6; ++s) {
        int row = p0 + s - 1;
        float4* dst = (float4*)(sb + s * 4096);
        if ((unsigned)row < 4096u) {
            const float4* src = (const float4*)(S + (size_t)row * 4096);
            dst[tid] = src[tid];
            dst[tid + 512] = src[tid + 512];
        } else {
            dst[tid] = make_float4(0.f, 0.f, 0.f, 0.f);
            dst[tid + 512] = make_float4(0.f, 0.f, 0.f, 0.f);
        }
    }
    __syncthreads();
    float* F1 = g_D[i] + (size_t)p0 * 4096;
    #pragma unroll
    for (int k = 0; k < 8; ++k) {
        int q = tid + (k << 9);
        #pragma unroll
        for (int qi = 0; qi < 4; ++qi) {
            float s = 0.f;
            #pragma unroll
            for (int d = -1; d <= 1; ++d) {
                int qq = q + d;
                if ((unsigned)qq < 4096u)
                    s += sb[(qi + d + 1) * 4096 + qq];
            }
            F1[(size_t)qi * 4096 + q] = s;
        }
    }
}

// -------- K5: fused fuse2 + masked softmax, output AT (transposed coords) --
__global__ void k_fuse2sm() {
    extern __shared__ float smf[];     // 3 * 4160 floats
    __shared__ float red[256];
    int i = blockIdx.z, pt = blockIdx.x, tid = threadIdx.x;
    const float* F1 = g_D[i];

    #pragma unroll
    for (int d = 0; d < 3; ++d) {
        int pz = pt + d - 1;
        float* dst = smf + d * 4160;
        if ((unsigned)pz < 4096u) {
            int rd = ((pz & 63) << 6) | (pz >> 6);
            const float* row = F1 + (size_t)rd * 4096;
            #pragma unroll
            for (int j = 0; j < 16; ++j) {
                int c = tid + j * 256;
                dst[(c & 63) * 65 + (c >> 6)] = row[c];
            }
        } else {
            #pragma unroll
            for (int j = 0; j < 16; ++j) {
                int c = tid + j * 256;
                dst[(c & 63) * 65 + (c >> 6)] = 0.f;
            }
        }
    }
    __syncthreads();

    float vals[16], msk[16];
    float mx = -3.4e38f;
    #pragma unroll
    for (int j = 0; j < 16; ++j) {
        int qt = tid + j * 256;
        float s = 0.f;
        #pragma unroll
        for (int d = 0; d < 3; ++d) {
            int z = qt + d - 1;
            if ((unsigned)z < 4096u)
                s += smf[d * 4160 + (z >> 6) * 65 + (z & 63)];
        }
        float m = g_mmT[qt];
        msk[j] = m;
        float v = s * m * 10.0f;
        vals[j] = v;
        mx = fmaxf(mx, v);
    }
    red[tid] = mx; __syncthreads();
    #pragma unroll
    for (int s = 128; s > 0; s >>= 1) { if (tid < s) red[tid] = fmaxf(red[tid], red[tid + s]); __syncthreads(); }
    mx = red[0]; __syncthreads();
    float sum = 0.f;
    #pragma unroll
    for (int j = 0; j < 16; ++j) { vals[j] = expf(vals[j] - mx); sum += vals[j]; }
    red[tid] = sum; __syncthreads();
    #pragma unroll
    for (int s = 128; s > 0; s >>= 1) { if (tid < s) red[tid] += red[tid + s]; __syncthreads(); }
    float inv = 1.0f / red[0];
    float* out = g_S[i] + (size_t)pt * 4096;
    #pragma unroll
    for (int j = 0; j < 16; ++j) {
        int qt = tid + j * 256;
        out[qt] = vals[j] * inv * msk[j];
    }
}

// ------ K7: build A-tilde (primed ordering, reads AT coalesced) -------------
__global__ void k_Abuild() {
    int i = blockIdx.z;
    int q0p = blockIdx.y;
    int lpp = blockIdx.x * 256 + threadIdx.x;
    int y0 = q0p / 65, x0 = q0p % 65;
    int vp = lpp / 65, up = lpp % 65;
    const float* AT = g_S[i];
    float s = 0.f;
    #pragma unroll
    for (int a = 0; a < 2; ++a) {
        int xr = x0 - a, ur = up - a;
        if ((unsigned)xr < 64u && (unsigned)ur < 64u) {
            #pragma unroll
            for (int bo = 0; bo < 2; ++bo) {
                int yr = y0 - bo, vr = vp - bo;
                if ((unsigned)yr < 64u && (unsigned)vr < 64u)
                    s += AT[(size_t)(yr * 64 + xr) * 4096 + (vr * 64 + ur)];
            }
        }
    }
    __nv_bfloat16 h, l;
    split_bf16(s, h, l);
    g_Ath[i][(size_t)q0p * MQP + lpp] = h;
    g_Atl[i][(size_t)q0p * MQP + lpp] = l;
}

// ------ K8: build Bt[n][lp'] (bf16 hi/lo, primed K ordering) ----------------
__global__ void k_Btbuild(const float* __restrict__ b) {
    int i = blockIdx.z;
    int n = blockIdx.y;
    int lpp = blockIdx.x * 256 + threadIdx.x;
    int par = n / IC, c = n - par * IC;
    int rx = par >> 1, ry = par & 1;
    int vp = lpp / 65, up = lpp % 65;
    int X = 2 * up + rx - 1, Y = 2 * vp + ry - 1;
    float val = 0.f;
    if (lpp < MQ && (unsigned)X < 128u && (unsigned)Y < 128u)
        val = b[(((size_t)i * IH + X) * IW + Y) * IC + c];
    __nv_bfloat16 h, l;
    split_bf16(val, h, l);
    g_Bth[i][(size_t)n * MQP + lpp] = h;
    g_Btl[i][(size_t)n * MQP + lpp] = l;
}

// ---------------- launch -----------------------------------------------------
extern "C" void kernel_launch(void* const* d_in, const int* in_sizes, int n_in,
                              void* d_out, int out_size) {
    const float* f    = (const float*)d_in[0];
    const float* b    = (const float*)d_in[1];
    const float* mask = (const float*)d_in[2];
    float* out = (float*)d_out;

    const int gemm_smem = 8 * TILEB * 3;      // 122880 B
    const int f2_smem   = 3 * 4160 * 4;       // 49920 B
    const int band_smem = 6 * 4096 * 4;       // 98304 B
    cudaFuncSetAttribute(k_gemm_mma<0>, cudaFuncAttributeMaxDynamicSharedMemorySize, gemm_smem);
    cudaFuncSetAttribute(k_gemm_mma<1>, cudaFuncAttributeMaxDynamicSharedMemorySize, gemm_smem);
    cudaFuncSetAttribute(k_fuse2sm, cudaFuncAttributeMaxDynamicSharedMemorySize, f2_smem);
    cudaFuncSetAttribute(k_score,  cudaFuncAttributeMaxDynamicSharedMemorySize, band_smem);
    cudaFuncSetAttribute(k_fuse1,  cudaFuncAttributeMaxDynamicSharedMemorySize, band_smem);

    k_pack    <<<dim3(4096, 1, NB), 192>>>(f, b);
    k_norm_mm <<<dim3(32,   1, NB), 128>>>(mask);
    k_gemm_mma<0><<<dim3(32, 32, NB), 256, gemm_smem>>>(nullptr);
    k_score   <<<dim3(1024, 1, NB), 512, band_smem>>>();
    k_fuse1   <<<dim3(1024, 1, NB), 512, band_smem>>>();
    k_fuse2sm <<<dim3(4096, 1, NB), 256, f2_smem>>>();
    k_Abuild  <<<dim3(17, MQ, NB), 256>>>();
    k_Btbuild <<<dim3(17, NOUT, NB), 256>>>(b);
    k_gemm_mma<1><<<dim3(6, 34, NB), 256, gemm_smem>>>(out);
}